// round 2
// baseline (speedup 1.0000x reference)
#include <cuda_runtime.h>
#include <cuda_bf16.h>

// out[i] = (|bits[i % 4096]| > 0.5) ? 1.0f : 0.0f for all 48*1024*1024 elements.
// Derivation: within a channel, idx = (x*WIDTH + y) % 4096 = j % 4096; the
// channel stride 1024*1024 is an exact multiple of 4096, so one 4096-float
// pattern tiles the entire (48,1024,1024) output 12288 times.

#define PATTERN_FLOATS 4096
#define PATTERN_VEC4   1024          // 4096 floats = 1024 float4
#define THREADS        256
#define BLOCKS         1184          // 148 SMs * 8 CTAs

__global__ __launch_bounds__(THREADS) void pattern_broadcast_kernel(
    const float* __restrict__ bits,
    float4* __restrict__ out,
    int n_chunks)                    // number of 4096-float repeats = out_size / 4096
{
    __shared__ float pat[PATTERN_FLOATS];

    const int t = threadIdx.x;

    // Build the 4096-value pattern cooperatively (16 loads/thread).
    #pragma unroll
    for (int i = 0; i < PATTERN_FLOATS / THREADS; i++) {
        int idx = t + i * THREADS;
        pat[idx] = (fabsf(bits[idx]) > 0.5f) ? 1.0f : 0.0f;
    }
    __syncthreads();

    // Hoist this thread's 4 float4 slices into registers (coalesced layout:
    // within a chunk, thread t owns vec4 indices t, t+256, t+512, t+768).
    const float4* pv = reinterpret_cast<const float4*>(pat);
    const float4 v0 = pv[t];
    const float4 v1 = pv[t + 256];
    const float4 v2 = pv[t + 512];
    const float4 v3 = pv[t + 768];

    // Grid-stride over pattern-sized chunks, 2 chunks per iteration for
    // deeper store MLP (8 independent STG.128 in flight per thread).
    int c = blockIdx.x;
    const int stride = gridDim.x;
    for (; c + stride < n_chunks; c += 2 * stride) {
        float4* o0 = out + (size_t)c * PATTERN_VEC4;
        float4* o1 = out + (size_t)(c + stride) * PATTERN_VEC4;
        o0[t]       = v0;
        o0[t + 256] = v1;
        o0[t + 512] = v2;
        o0[t + 768] = v3;
        o1[t]       = v0;
        o1[t + 256] = v1;
        o1[t + 512] = v2;
        o1[t + 768] = v3;
    }
    if (c < n_chunks) {
        float4* o = out + (size_t)c * PATTERN_VEC4;
        o[t]       = v0;
        o[t + 256] = v1;
        o[t + 512] = v2;
        o[t + 768] = v3;
    }
}

extern "C" void kernel_launch(void* const* d_in, const int* in_sizes, int n_in,
                              void* d_out, int out_size) {
    const float* bits = (const float*)d_in[0];
    float4* out = (float4*)d_out;

    // out_size = 48 * 1024 * 1024, an exact multiple of 4096.
    int n_chunks = out_size / PATTERN_FLOATS;   // 12288

    pattern_broadcast_kernel<<<BLOCKS, THREADS>>>(bits, out, n_chunks);
}